// round 4
// baseline (speedup 1.0000x reference)
#include <cuda_runtime.h>
#include <cuda_bf16.h>
#include <cstdint>

#define L    1024
#define CZ   128
#define NT   16    // tiles per dim (64-wide)
#define NSC  32    // col-partial slots (2 per m-tile)
#define NP   32    // stage1 passes (2 m per pass)

// ---------------- scratch ----------------
__device__ float g_PartC[(size_t)NSC * L * CZ];  // [slot][l][c] 16MB
__device__ float g_PartR[(size_t)NT * L * CZ];   // [by][m][c]   8MB
__device__ float g_maskC[L];
__device__ float g_maskR[L];
__device__ float g_ssc[L * CZ];
__device__ float g_ssr[L * CZ];
__device__ float g_u[CZ];
__device__ float g_v[CZ];

// ---------------- helpers ----------------
__device__ __forceinline__ void cp16(uint32_t dst, const void* src) {
  asm volatile("cp.async.cg.shared.global [%0], [%1], 16;" :: "r"(dst), "l"(src));
}
__device__ __forceinline__ void cp_commit() { asm volatile("cp.async.commit_group;"); }
__device__ __forceinline__ uint32_t f2tf(float x) {
  uint32_t r; asm("cvt.rna.tf32.f32 %0, %1;" : "=r"(r) : "f"(x)); return r;
}

// ---------------- mask sums ----------------
__global__ void k_masksums(const float* __restrict__ mask) {
  __shared__ float red[2][256];
  int i = blockIdx.x, tid = threadIdx.x;
  float sc = 0.f, sr = 0.f;
  for (int j = tid; j < L; j += 256) {
    sc += mask[(size_t)i * L + j];
    sr += mask[(size_t)j * L + i];
  }
  red[0][tid] = sc; red[1][tid] = sr;
  __syncthreads();
  for (int s = 128; s > 0; s >>= 1) {
    if (tid < s) { red[0][tid] += red[0][tid + s]; red[1][tid] += red[1][tid + s]; }
    __syncthreads();
  }
  if (tid == 0) { g_maskC[i] = red[0][0]; g_maskR[i] = red[1][0]; }
}

// ---------------- prep: u = ln_b@w1^T + b1, v = ln_g@w1^T ----------------
__global__ void k_prep(const float* __restrict__ w1, const float* __restrict__ b1,
                       const float* __restrict__ ln_g, const float* __restrict__ ln_b) {
  int d = threadIdx.x;
  float u = b1[d], v = 0.f;
  for (int c = 0; c < CZ; c++) {
    float w = w1[d * CZ + c];
    u += ln_b[c] * w;
    v += ln_g[c] * w;
  }
  g_u[d] = u; g_v[d] = v;
}

// ---------------- stage 1: pipelined raw-z bf16 GEMM + LN-fold epilogue ----------------
__global__ __launch_bounds__(256, 1) void k_stage1(
    const float* __restrict__ s_z, const float* __restrict__ mask,
    const float* __restrict__ ln_g, const float* __restrict__ w1) {
  extern __shared__ char smem_raw[];
  __nv_bfloat16* sW    = (__nv_bfloat16*)smem_raw;            // [128][136] W~ = g*w1
  float*         sZ    = (float*)(sW + 128 * 136);            // [2][128][128]
  __nv_bfloat16* sA    = (__nv_bfloat16*)(sZ + 2 * 128 * 128);// [128][136] raw z bf16
  float*         sMask = (float*)(sA + 128 * 136);            // [64][68]
  float*         sMu   = sMask + 64 * 68;                     // [128]
  float*         sRs   = sMu + 128;
  float*         sU    = sRs + 128;
  float*         sV    = sU + 128;
  float*         sRow  = sV + 128;                            // [2][128]

  const int tid = threadIdx.x, lane = tid & 31, warp = tid >> 5;
  const int g = lane >> 2, q = lane & 3;
  const int wm = warp >> 1, wn = warp & 1;                    // 4 x 2 warps, tile 32x64
  const int bx = blockIdx.x, by = blockIdx.y;
  const int m0 = bx * 64, l0 = by * 64;
  const int par = wm >> 1;                                    // m parity handled by this warp

  const uint32_t szBase = (uint32_t)__cvta_generic_to_shared(sZ);

  // init: sW = bf16(w1 * g), mask tile, u/v, sRow
  for (int i = tid; i < 128 * 128; i += 256) {
    int d = i >> 7, c = i & 127;
    sW[d * 136 + c] = __float2bfloat16(w1[i] * ln_g[c]);
  }
  if (tid < 128) { sU[tid] = g_u[tid]; sV[tid] = g_v[tid]; }
  for (int i = tid; i < 64 * 16; i += 256) {
    int r = i >> 4, c4 = (i & 15) << 2;
    float4 mv = *(const float4*)(mask + (size_t)(l0 + r) * L + m0 + c4);
    *(float4*)(sMask + r * 68 + c4) = mv;
  }
  sRow[tid] = 0.f;

  // cp.async issue of one pass (128 rows = 2 m x 64 l)
  const int cr = tid >> 1, chalf = tid & 1;
  const int cl = cr & 63, cp = cr >> 6;
  auto issue = [&](int it, int buf) {
    const float* src = s_z + ((size_t)(l0 + cl) * L + (m0 + 2 * it + cp)) * CZ + chalf * 64;
    uint32_t dst = szBase + (uint32_t)(buf * 16384 + cr * 128 + chalf * 64) * 4;
    #pragma unroll
    for (int j = 0; j < 16; j++) cp16(dst + j * 16, src + j * 4);
    cp_commit();
  };

  float colAcc[2][8][4];
  #pragma unroll
  for (int a = 0; a < 2; a++)
    #pragma unroll
    for (int b = 0; b < 8; b++)
      #pragma unroll
      for (int c = 0; c < 4; c++) colAcc[a][b][c] = 0.f;

  issue(0, 0);

  for (int it = 0; it < NP; it++) {
    const int buf = it & 1;
    if (it + 1 < NP) {
      issue(it + 1, buf ^ 1);
      asm volatile("cp.async.wait_group 1;");
    } else {
      asm volatile("cp.async.wait_group 0;");
    }
    __syncthreads();

    // convert 16 rows per warp: raw z -> bf16 sA; fp32 sums -> mu, rs
    {
      const float* zb = sZ + buf * 16384;
      #pragma unroll
      for (int rr = 0; rr < 16; rr++) {
        int row = warp * 16 + rr;
        float4 v = *(const float4*)(zb + row * 128 + lane * 4);
        __nv_bfloat162 p0 = __floats2bfloat162_rn(v.x, v.y);
        __nv_bfloat162 p1 = __floats2bfloat162_rn(v.z, v.w);
        *(uint2*)(sA + row * 136 + lane * 4) =
            make_uint2(*(uint32_t*)&p0, *(uint32_t*)&p1);
        float s  = v.x + v.y + v.z + v.w;
        float s2 = v.x * v.x + v.y * v.y + v.z * v.z + v.w * v.w;
        #pragma unroll
        for (int o = 16; o > 0; o >>= 1) {
          s  += __shfl_xor_sync(0xffffffffu, s, o);
          s2 += __shfl_xor_sync(0xffffffffu, s2, o);
        }
        if (lane == 0) {
          float mu  = s * (1.f / 128.f);
          float var = fmaf(s2, 1.f / 128.f, -mu * mu);
          sMu[row] = mu;
          sRs[row] = rsqrtf(var + 1e-5f);
        }
      }
    }
    __syncthreads();

    // MMA: 128x128x128, warp tile 32x64
    float acc[2][8][4];
    #pragma unroll
    for (int a = 0; a < 2; a++)
      #pragma unroll
      for (int b = 0; b < 8; b++)
        #pragma unroll
        for (int c = 0; c < 4; c++) acc[a][b][c] = 0.f;

    #pragma unroll
    for (int ks = 0; ks < 8; ks++) {
      const int k0 = ks * 16;
      uint32_t af[2][4];
      #pragma unroll
      for (int mt = 0; mt < 2; mt++) {
        int R = wm * 32 + mt * 16;
        af[mt][0] = *(const uint32_t*)(sA + (R + g    ) * 136 + k0     + q * 2);
        af[mt][1] = *(const uint32_t*)(sA + (R + g + 8) * 136 + k0     + q * 2);
        af[mt][2] = *(const uint32_t*)(sA + (R + g    ) * 136 + k0 + 8 + q * 2);
        af[mt][3] = *(const uint32_t*)(sA + (R + g + 8) * 136 + k0 + 8 + q * 2);
      }
      #pragma unroll
      for (int nb = 0; nb < 8; nb++) {
        const int n = wn * 64 + nb * 8 + g;
        uint32_t b0 = *(const uint32_t*)(sW + n * 136 + k0     + q * 2);
        uint32_t b1 = *(const uint32_t*)(sW + n * 136 + k0 + 8 + q * 2);
        #pragma unroll
        for (int mt = 0; mt < 2; mt++) {
          asm volatile(
            "mma.sync.aligned.m16n8k16.row.col.f32.bf16.bf16.f32 "
            "{%0,%1,%2,%3}, {%4,%5,%6,%7}, {%8,%9}, {%0,%1,%2,%3};\n"
            : "+f"(acc[mt][nb][0]), "+f"(acc[mt][nb][1]),
              "+f"(acc[mt][nb][2]), "+f"(acc[mt][nb][3])
            : "r"(af[mt][0]), "r"(af[mt][1]), "r"(af[mt][2]), "r"(af[mt][3]),
              "r"(b0), "r"(b1));
        }
      }
    }

    // epilogue: h = rs*acc + u - mu*rs*v, relu, *mask; accumulate reductions
    const int mi = 2 * it + par;
    float rsum[16];
    #pragma unroll
    for (int i2 = 0; i2 < 16; i2++) rsum[i2] = 0.f;
    #pragma unroll
    for (int mt = 0; mt < 2; mt++) {
      const int R = wm * 32 + mt * 16;
      const int row0 = R + g, row1 = R + g + 8;
      const int lr0 = row0 - par * 64, lr1 = row1 - par * 64;
      float mu0 = sMu[row0], rs0 = sRs[row0];
      float mu1 = sMu[row1], rs1 = sRs[row1];
      float mk0 = sMask[lr0 * 68 + mi];
      float mk1 = sMask[lr1 * 68 + mi];
      float c0r0 = -mu0 * rs0, c1r1 = -mu1 * rs1;
      #pragma unroll
      for (int nb = 0; nb < 8; nb++) {
        const int col = wn * 64 + nb * 8 + q * 2;
        float u0 = sU[col], v0 = sV[col], u1 = sU[col + 1], v1 = sV[col + 1];
        float h0 = fmaxf(fmaf(rs0, acc[mt][nb][0], fmaf(c0r0, v0, u0)), 0.f) * mk0;
        float h1 = fmaxf(fmaf(rs0, acc[mt][nb][1], fmaf(c0r0, v1, u1)), 0.f) * mk0;
        float h2 = fmaxf(fmaf(rs1, acc[mt][nb][2], fmaf(c1r1, v0, u0)), 0.f) * mk1;
        float h3 = fmaxf(fmaf(rs1, acc[mt][nb][3], fmaf(c1r1, v1, u1)), 0.f) * mk1;
        colAcc[mt][nb][0] += h0; colAcc[mt][nb][1] += h1;
        colAcc[mt][nb][2] += h2; colAcc[mt][nb][3] += h3;
        rsum[nb * 2]     += h0 + h2;
        rsum[nb * 2 + 1] += h1 + h3;
      }
    }
    #pragma unroll
    for (int off = 4; off < 32; off <<= 1) {
      #pragma unroll
      for (int i2 = 0; i2 < 16; i2++)
        rsum[i2] += __shfl_xor_sync(0xffffffffu, rsum[i2], off);
    }
    if (lane < 4) {
      #pragma unroll
      for (int nb = 0; nb < 8; nb++) {
        atomicAdd(&sRow[par * 128 + wn * 64 + nb * 8 + lane * 2    ], rsum[nb * 2]);
        atomicAdd(&sRow[par * 128 + wn * 64 + nb * 8 + lane * 2 + 1], rsum[nb * 2 + 1]);
      }
    }
    __syncthreads();
    {
      int p2 = tid >> 7, c = tid & 127;
      int m = m0 + 2 * it + p2;
      g_PartR[((size_t)by * L + m) * CZ + c] = sRow[tid];
      sRow[tid] = 0.f;
    }
  }

  // write column partials: slot = bx*2 + parity
  #pragma unroll
  for (int mt = 0; mt < 2; mt++) {
    const int R = wm * 32 + mt * 16;
    const int lA = R - par * 64 + g, lB = lA + 8;
    #pragma unroll
    for (int nb = 0; nb < 8; nb++) {
      const int col = wn * 64 + nb * 8 + q * 2;
      size_t base = (size_t)(bx * 2 + par) * L * CZ;
      float2 vA = make_float2(colAcc[mt][nb][0], colAcc[mt][nb][1]);
      float2 vB = make_float2(colAcc[mt][nb][2], colAcc[mt][nb][3]);
      *(float2*)(g_PartC + base + (size_t)(l0 + lA) * CZ + col) = vA;
      *(float2*)(g_PartC + base + (size_t)(l0 + lB) * CZ + col) = vB;
    }
  }
}

// ---------------- stage 2: reduce partials, apply w2/b2, normalize ----------------
__global__ void k_stage2(const float* __restrict__ w2, const float* __restrict__ b2) {
  __shared__ float sv[128];
  const int i = blockIdx.x, tid = threadIdx.x;
  {
    float a = 0.f;
    #pragma unroll
    for (int t = 0; t < NSC; t++) a += g_PartC[((size_t)t * L + i) * CZ + tid];
    sv[tid] = a;
    __syncthreads();
    float mc = g_maskC[i];
    const float4* wr = (const float4*)(w2 + tid * 128);
    float dot = 0.f;
    #pragma unroll 8
    for (int c = 0; c < 32; c++) {
      float4 wv = wr[c];
      dot += sv[c*4] * wv.x + sv[c*4+1] * wv.y + sv[c*4+2] * wv.z + sv[c*4+3] * wv.w;
    }
    g_ssc[i * CZ + tid] = (dot + b2[tid] * mc) / fmaxf(mc, 1.f);
    __syncthreads();
  }
  {
    float a = 0.f;
    #pragma unroll
    for (int t = 0; t < NT; t++) a += g_PartR[((size_t)t * L + i) * CZ + tid];
    sv[tid] = a;
    __syncthreads();
    float mr = g_maskR[i];
    const float4* wr = (const float4*)(w2 + tid * 128);
    float dot = 0.f;
    #pragma unroll 8
    for (int c = 0; c < 32; c++) {
      float4 wv = wr[c];
      dot += sv[c*4] * wv.x + sv[c*4+1] * wv.y + sv[c*4+2] * wv.z + sv[c*4+3] * wv.w;
    }
    g_ssr[i * CZ + tid] = (dot + b2[tid] * mr) / fmaxf(mr, 1.f);
  }
}

// ---------------- stage 3: out = cat @ wc^T + bc, tf32, pipelined ----------------
__global__ __launch_bounds__(256) void k_stage3(
    const float* __restrict__ s_s_in, const float* __restrict__ wc,
    const float* __restrict__ bc, float* __restrict__ out) {
  extern __shared__ float sm3[];
  float* sA3 = sm3;                 // [2][64][68]
  float* sB3 = sm3 + 2 * 64 * 68;   // [2][64][68]
  const uint32_t aBase = (uint32_t)__cvta_generic_to_shared(sA3);
  const uint32_t bBase = (uint32_t)__cvta_generic_to_shared(sB3);

  const int tid = threadIdx.x, lane = tid & 31, warp = tid >> 5;
  const int g = lane >> 2, q = lane & 3;
  const int wm = warp >> 1, wn = warp & 1;          // 4 x 2 warps, tile 16x32
  const int d0 = blockIdx.x * 64, t0 = blockIdx.y * 64;

  const int cr = tid >> 2, cseg = tid & 3;

  auto issue = [&](int kc, int buf) {
    const float* srcA; int strideA, koffA;
    if (kc < 2)      { srcA = g_ssc;  strideA = 128;  koffA = kc * 64; }
    else if (kc < 4) { srcA = g_ssr;  strideA = 128;  koffA = (kc - 2) * 64; }
    else             { srcA = s_s_in; strideA = 1024; koffA = (kc - 4) * 64; }
    const float* sa = srcA + (size_t)(t0 + cr) * strideA + koffA + cseg * 16;
    const float* sb = wc + (size_t)(d0 + cr) * 1280 + kc * 64 + cseg * 16;
    uint32_t da = aBase + (uint32_t)(buf * 4352 + cr * 68 + cseg * 16) * 4;
    uint32_t db = bBase + (uint32_t)(buf * 4352 + cr * 68 + cseg * 16) * 4;
    #pragma unroll
    for (int j = 0; j < 4; j++) { cp16(da + j * 16, sa + j * 4); cp16(db + j * 16, sb + j * 4); }
    cp_commit();
  };

  float acc[4][4];
  #pragma unroll
  for (int b = 0; b < 4; b++)
    #pragma unroll
    for (int c = 0; c < 4; c++) acc[b][c] = 0.f;

  issue(0, 0);

  for (int kc = 0; kc < 20; kc++) {
    const int buf = kc & 1;
    if (kc + 1 < 20) {
      issue(kc + 1, buf ^ 1);
      asm volatile("cp.async.wait_group 1;");
    } else {
      asm volatile("cp.async.wait_group 0;");
    }
    __syncthreads();

    const float* A = sA3 + buf * 4352;
    const float* B = sB3 + buf * 4352;
    const int R = wm * 16;
    #pragma unroll
    for (int ks = 0; ks < 8; ks++) {
      const int k0 = ks * 8;
      uint32_t a0 = f2tf(A[(R + g    ) * 68 + k0 + q    ]);
      uint32_t a1 = f2tf(A[(R + g + 8) * 68 + k0 + q    ]);
      uint32_t a2 = f2tf(A[(R + g    ) * 68 + k0 + q + 4]);
      uint32_t a3 = f2tf(A[(R + g + 8) * 68 + k0 + q + 4]);
      #pragma unroll
      for (int nb = 0; nb < 4; nb++) {
        const int n = wn * 32 + nb * 8 + g;
        uint32_t b0 = f2tf(B[n * 68 + k0 + q    ]);
        uint32_t b1 = f2tf(B[n * 68 + k0 + q + 4]);
        asm volatile(
          "mma.sync.aligned.m16n8k8.row.col.f32.tf32.tf32.f32 "
          "{%0,%1,%2,%3}, {%4,%5,%6,%7}, {%8,%9}, {%0,%1,%2,%3};\n"
          : "+f"(acc[nb][0]), "+f"(acc[nb][1]), "+f"(acc[nb][2]), "+f"(acc[nb][3])
          : "r"(a0), "r"(a1), "r"(a2), "r"(a3), "r"(b0), "r"(b1));
      }
    }
    __syncthreads();
  }

  const int r0 = t0 + wm * 16 + g;
  #pragma unroll
  for (int nb = 0; nb < 4; nb++) {
    const int c = d0 + wn * 32 + nb * 8 + q * 2;
    float bc0 = bc[c], bc1 = bc[c + 1];
    *(float2*)(out + (size_t)r0 * L + c)       = make_float2(acc[nb][0] + bc0, acc[nb][1] + bc1);
    *(float2*)(out + (size_t)(r0 + 8) * L + c) = make_float2(acc[nb][2] + bc0, acc[nb][3] + bc1);
  }
}

// ---------------- launch ----------------
extern "C" void kernel_launch(void* const* d_in, const int* in_sizes, int n_in,
                              void* d_out, int out_size) {
  const float* s_z    = (const float*)d_in[0];
  const float* s_s_in = (const float*)d_in[1];
  const float* pmask  = (const float*)d_in[2];
  const float* ln_g   = (const float*)d_in[3];
  const float* ln_b   = (const float*)d_in[4];
  const float* w1     = (const float*)d_in[5];
  const float* b1     = (const float*)d_in[6];
  const float* w2     = (const float*)d_in[7];
  const float* b2     = (const float*)d_in[8];
  const float* wc     = (const float*)d_in[9];
  const float* bc     = (const float*)d_in[10];
  float* out = (float*)d_out;

  const int smem1 = 128*136*2 + 2*128*128*4 + 128*136*2 + 64*68*4 + 4*128*4 + 256*4; // 221184
  const int smem3 = 2 * 2 * 64 * 68 * 4;                                             // 69632
  cudaFuncSetAttribute(k_stage1, cudaFuncAttributeMaxDynamicSharedMemorySize, smem1);
  cudaFuncSetAttribute(k_stage3, cudaFuncAttributeMaxDynamicSharedMemorySize, smem3);

  k_masksums<<<L, 256>>>(pmask);
  k_prep<<<1, CZ>>>(w1, b1, ln_g, ln_b);
  k_stage1<<<dim3(NT, NT), 256, smem1>>>(s_z, pmask, ln_g, w1);
  k_stage2<<<L, 128>>>(w2, b2);
  k_stage3<<<dim3(16, 16), 256, smem3>>>(s_s_in, wc, bc, out);
}

// round 7
// speedup vs baseline: 1.2016x; 1.2016x over previous
#include <cuda_runtime.h>
#include <cuda_bf16.h>
#include <cstdint>

#define L    1024
#define CZ   128
#define NT   16    // 64-wide tiles per dim

// ---------------- scratch ----------------
__device__ float g_PartC[(size_t)NT * L * CZ];   // [bx][l][c] 8MB
__device__ float g_PartR[(size_t)NT * L * CZ];   // [by][m][c] 8MB
__device__ float g_maskC[L];
__device__ float g_maskR[L];
__device__ float g_ssc[L * CZ];
__device__ float g_ssr[L * CZ];
__device__ float g_u[CZ];
__device__ float g_v[CZ];

// ---------------- helpers ----------------
__device__ __forceinline__ void cp16(uint32_t dst, const void* src) {
  asm volatile("cp.async.cg.shared.global [%0], [%1], 16;" :: "r"(dst), "l"(src));
}
__device__ __forceinline__ void cp_commit() { asm volatile("cp.async.commit_group;"); }
__device__ __forceinline__ uint32_t f2tf(float x) {
  uint32_t r; asm("cvt.rna.tf32.f32 %0, %1;" : "=r"(r) : "f"(x)); return r;
}
__device__ __forceinline__ void ldsm_x4(uint32_t& r0, uint32_t& r1, uint32_t& r2,
                                        uint32_t& r3, uint32_t addr) {
  asm volatile("ldmatrix.sync.aligned.m8n8.x4.shared.b16 {%0,%1,%2,%3}, [%4];"
               : "=r"(r0), "=r"(r1), "=r"(r2), "=r"(r3) : "r"(addr));
}

// ---------------- mask sums ----------------
__global__ void k_masksums(const float* __restrict__ mask) {
  __shared__ float red[2][256];
  int i = blockIdx.x, tid = threadIdx.x;
  float sc = 0.f, sr = 0.f;
  for (int j = tid; j < L; j += 256) {
    sc += mask[(size_t)i * L + j];
    sr += mask[(size_t)j * L + i];
  }
  red[0][tid] = sc; red[1][tid] = sr;
  __syncthreads();
  for (int s = 128; s > 0; s >>= 1) {
    if (tid < s) { red[0][tid] += red[0][tid + s]; red[1][tid] += red[1][tid + s]; }
    __syncthreads();
  }
  if (tid == 0) { g_maskC[i] = red[0][0]; g_maskR[i] = red[1][0]; }
}

// ---------------- prep: u = ln_b@w1^T + b1, v = ln_g@w1^T ----------------
__global__ void k_prep(const float* __restrict__ w1, const float* __restrict__ b1,
                       const float* __restrict__ ln_g, const float* __restrict__ ln_b) {
  int d = threadIdx.x;
  float u = b1[d], v = 0.f;
  for (int c = 0; c < CZ; c++) {
    float w = w1[d * CZ + c];
    u += ln_b[c] * w;
    v += ln_g[c] * w;
  }
  g_u[d] = u; g_v[d] = v;
}

// ---------------- stage 1 ----------------
__global__ __launch_bounds__(256, 1) void k_stage1(
    const float* __restrict__ s_z, const float* __restrict__ mask,
    const float* __restrict__ ln_g, const float* __restrict__ w1) {
  extern __shared__ char smem_raw[];
  __nv_bfloat16* sW    = (__nv_bfloat16*)smem_raw;      // [128][136] W~ = g*w1 (bf16)
  __nv_bfloat16* sA    = sW + 128 * 136;                // [64][136] raw z (bf16)
  float*         sMask = (float*)(sA + 64 * 136);       // [64][68]
  float*         sMu   = sMask + 64 * 68;               // [64]
  float*         sRs   = sMu + 64;                      // [64]
  float*         sU    = sRs + 64;                      // [128]
  float*         sV    = sU + 128;                      // [128]
  float*         sRow  = sV + 128;                      // [128]

  const int tid = threadIdx.x, lane = tid & 31, warp = tid >> 5;
  const int g = lane >> 2, q = lane & 3;
  const int wm = warp >> 1, wn = warp & 1;              // 4 x 2 warps, tile 16x64
  const int bx = blockIdx.x, by = blockIdx.y;
  const int m0 = bx * 64, l0 = by * 64;
  const int arow = wm * 16;

  const uint32_t aB = (uint32_t)__cvta_generic_to_shared(sA);
  const uint32_t wB = (uint32_t)__cvta_generic_to_shared(sW);

  // init
  for (int i = tid; i < 128 * 128; i += 256) {
    int d = i >> 7, c = i & 127;
    sW[d * 136 + c] = __float2bfloat16(w1[i] * ln_g[c]);
  }
  if (tid < 128) { sU[tid] = g_u[tid]; sV[tid] = g_v[tid]; sRow[tid] = 0.f; }
  for (int i = tid; i < 64 * 16; i += 256) {
    int r = i >> 4, c4 = (i & 15) << 2;
    float4 mv = *(const float4*)(mask + (size_t)(l0 + r) * L + m0 + c4);
    *(float4*)(sMask + r * 68 + c4) = mv;
  }

  // ldmatrix address bases (byte units into smem)
  const uint32_t aAddrBase =
      aB + (uint32_t)(((arow + (lane & 15)) * 136 + ((lane >> 4) << 3)) * 2);
  const uint32_t bRow  = wn * 64 + ((lane >> 4) << 3) + (lane & 7);
  const uint32_t bKoff = ((lane >> 3) & 1) << 3;
  const uint32_t bAddrBase = wB + (uint32_t)((bRow * 136 + bKoff) * 2);

  float colAcc[8][4];
  #pragma unroll
  for (int b = 0; b < 8; b++)
    #pragma unroll
    for (int c = 0; c < 4; c++) colAcc[b][c] = 0.f;

  // preload mi = 0
  float4 cur[8], nxt[8];
  #pragma unroll
  for (int r8 = 0; r8 < 8; r8++)
    cur[r8] = *(const float4*)(s_z + ((size_t)(l0 + warp * 8 + r8) * L + m0) * CZ + lane * 4);

  for (int mi = 0; mi < 64; mi++) {
    const int m = m0 + mi;
    // prefetch mi+1
    if (mi < 63) {
      #pragma unroll
      for (int r8 = 0; r8 < 8; r8++)
        nxt[r8] = *(const float4*)(s_z + ((size_t)(l0 + warp * 8 + r8) * L + m + 1) * CZ + lane * 4);
    }
    // pack raw z -> bf16 sA (no LN dependency), compute per-row stats
    #pragma unroll
    for (int r8 = 0; r8 < 8; r8++) {
      float4 v = cur[r8];
      int row = warp * 8 + r8;
      __nv_bfloat162 p0 = __floats2bfloat162_rn(v.x, v.y);
      __nv_bfloat162 p1 = __floats2bfloat162_rn(v.z, v.w);
      *(uint2*)(sA + row * 136 + lane * 4) = make_uint2(*(uint32_t*)&p0, *(uint32_t*)&p1);
      float s  = v.x + v.y + v.z + v.w;
      float s2 = v.x * v.x + v.y * v.y + v.z * v.z + v.w * v.w;
      #pragma unroll
      for (int o = 16; o > 0; o >>= 1) {
        s  += __shfl_xor_sync(0xffffffffu, s, o);
        s2 += __shfl_xor_sync(0xffffffffu, s2, o);
      }
      if (lane == 0) {
        float mu  = s * (1.f / 128.f);
        float var = fmaf(s2, 1.f / 128.f, -mu * mu);
        sMu[row] = mu;
        sRs[row] = rsqrtf(var + 1e-5f);
      }
    }
    __syncthreads();

    // MMA: h[64 x 128] = sA @ sW^T via ldmatrix + mma.sync
    float acc[8][4];
    #pragma unroll
    for (int b = 0; b < 8; b++)
      #pragma unroll
      for (int c = 0; c < 4; c++) acc[b][c] = 0.f;

    #pragma unroll
    for (int ks = 0; ks < 8; ks++) {
      const uint32_t kByte = (uint32_t)(ks * 16 * 2);
      uint32_t a0, a1, a2, a3;
      ldsm_x4(a0, a1, a2, a3, aAddrBase + kByte);
      #pragma unroll
      for (int p = 0; p < 4; p++) {
        uint32_t b0, b1, b2, b3;
        ldsm_x4(b0, b1, b2, b3, bAddrBase + kByte + (uint32_t)(p * 16 * 136 * 2));
        asm volatile(
          "mma.sync.aligned.m16n8k16.row.col.f32.bf16.bf16.f32 "
          "{%0,%1,%2,%3}, {%4,%5,%6,%7}, {%8,%9}, {%0,%1,%2,%3};\n"
          : "+f"(acc[2*p][0]), "+f"(acc[2*p][1]), "+f"(acc[2*p][2]), "+f"(acc[2*p][3])
          : "r"(a0), "r"(a1), "r"(a2), "r"(a3), "r"(b0), "r"(b1));
        asm volatile(
          "mma.sync.aligned.m16n8k16.row.col.f32.bf16.bf16.f32 "
          "{%0,%1,%2,%3}, {%4,%5,%6,%7}, {%8,%9}, {%0,%1,%2,%3};\n"
          : "+f"(acc[2*p+1][0]), "+f"(acc[2*p+1][1]), "+f"(acc[2*p+1][2]), "+f"(acc[2*p+1][3])
          : "r"(a0), "r"(a1), "r"(a2), "r"(a3), "r"(b2), "r"(b3));
      }
    }

    // epilogue: h = rs*acc + (u - mu*rs*v), relu, *mask; reductions
    const int row0 = arow + g, row1 = arow + g + 8;
    float mu0 = sMu[row0], rs0 = sRs[row0];
    float mu1 = sMu[row1], rs1 = sRs[row1];
    float mk0 = sMask[row0 * 68 + mi];
    float mk1 = sMask[row1 * 68 + mi];
    float c0 = -mu0 * rs0, c1 = -mu1 * rs1;
    float rsum[16];
    #pragma unroll
    for (int nb = 0; nb < 8; nb++) {
      const int col = wn * 64 + nb * 8 + q * 2;
      float u0 = sU[col], v0 = sV[col], u1 = sU[col + 1], v1 = sV[col + 1];
      float h0 = fmaxf(fmaf(rs0, acc[nb][0], fmaf(c0, v0, u0)), 0.f) * mk0;
      float h1 = fmaxf(fmaf(rs0, acc[nb][1], fmaf(c0, v1, u1)), 0.f) * mk0;
      float h2 = fmaxf(fmaf(rs1, acc[nb][2], fmaf(c1, v0, u0)), 0.f) * mk1;
      float h3 = fmaxf(fmaf(rs1, acc[nb][3], fmaf(c1, v1, u1)), 0.f) * mk1;
      colAcc[nb][0] += h0; colAcc[nb][1] += h1;
      colAcc[nb][2] += h2; colAcc[nb][3] += h3;
      rsum[nb * 2]     = h0 + h2;
      rsum[nb * 2 + 1] = h1 + h3;
    }
    #pragma unroll
    for (int off = 4; off < 32; off <<= 1) {
      #pragma unroll
      for (int i2 = 0; i2 < 16; i2++)
        rsum[i2] += __shfl_xor_sync(0xffffffffu, rsum[i2], off);
    }
    if (lane < 4) {
      #pragma unroll
      for (int nb = 0; nb < 8; nb++) {
        atomicAdd(&sRow[wn * 64 + nb * 8 + lane * 2    ], rsum[nb * 2]);
        atomicAdd(&sRow[wn * 64 + nb * 8 + lane * 2 + 1], rsum[nb * 2 + 1]);
      }
    }
    __syncthreads();
    if (tid < 128) {
      g_PartR[((size_t)by * L + m) * CZ + tid] = sRow[tid];
      sRow[tid] = 0.f;
    }
    // rotate prefetch
    #pragma unroll
    for (int r8 = 0; r8 < 8; r8++) cur[r8] = nxt[r8];
  }

  // write column partials
  #pragma unroll
  for (int nb = 0; nb < 8; nb++) {
    const int col = wn * 64 + nb * 8 + q * 2;
    const int r0 = arow + g, r1 = r0 + 8;
    size_t base = (size_t)bx * L * CZ;
    *(float2*)(g_PartC + base + (size_t)(l0 + r0) * CZ + col) =
        make_float2(colAcc[nb][0], colAcc[nb][1]);
    *(float2*)(g_PartC + base + (size_t)(l0 + r1) * CZ + col) =
        make_float2(colAcc[nb][2], colAcc[nb][3]);
  }
}

// ---------------- stage 2: w2 cached in smem, 8 rows per block ----------------
__global__ __launch_bounds__(256) void k_stage2(const float* __restrict__ w2,
                                                const float* __restrict__ b2) {
  extern __shared__ float w2s[];          // [128][129]
  __shared__ float sv[2][128];
  const int tid = threadIdx.x;
  const int half = tid >> 7, d = tid & 127;

  for (int i = tid; i < 128 * 128; i += 256) {
    int r = i >> 7, c = i & 127;
    w2s[r * 129 + c] = w2[i];
  }
  const float bd = b2[d];
  const float* P = half ? g_PartR : g_PartC;
  float* O = half ? g_ssr : g_ssc;
  const float* M = half ? g_maskR : g_maskC;
  __syncthreads();

  for (int ii = 0; ii < 8; ii++) {
    const int i = blockIdx.x * 8 + ii;
    float a = 0.f;
    #pragma unroll
    for (int t = 0; t < NT; t++) a += P[((size_t)t * L + i) * CZ + d];
    if (ii) __syncthreads();
    sv[half][d] = a;
    __syncthreads();
    float m = M[i];
    float dot = 0.f;
    const float* wr = w2s + d * 129;
    #pragma unroll 16
    for (int k = 0; k < 128; k++) dot += sv[half][k] * wr[k];
    O[i * CZ + d] = (dot + bd * m) / fmaxf(m, 1.f);
  }
}

// ---------------- stage 3: out = cat @ wc^T + bc, tf32, pipelined ----------------
__global__ __launch_bounds__(256) void k_stage3(
    const float* __restrict__ s_s_in, const float* __restrict__ wc,
    const float* __restrict__ bc, float* __restrict__ out) {
  extern __shared__ float sm3[];
  float* sA3 = sm3;                 // [2][64][68]
  float* sB3 = sm3 + 2 * 64 * 68;   // [2][64][68]
  const uint32_t aBase = (uint32_t)__cvta_generic_to_shared(sA3);
  const uint32_t bBase = (uint32_t)__cvta_generic_to_shared(sB3);

  const int tid = threadIdx.x, lane = tid & 31, warp = tid >> 5;
  const int g = lane >> 2, q = lane & 3;
  const int wm = warp >> 1, wn = warp & 1;          // 4 x 2 warps, tile 16x32
  const int d0 = blockIdx.x * 64, t0 = blockIdx.y * 64;

  const int cr = tid >> 2, cseg = tid & 3;

  auto issue = [&](int kc, int buf) {
    const float* srcA; int strideA, koffA;
    if (kc < 2)      { srcA = g_ssc;  strideA = 128;  koffA = kc * 64; }
    else if (kc < 4) { srcA = g_ssr;  strideA = 128;  koffA = (kc - 2) * 64; }
    else             { srcA = s_s_in; strideA = 1024; koffA = (kc - 4) * 64; }
    const float* sa = srcA + (size_t)(t0 + cr) * strideA + koffA + cseg * 16;
    const float* sb = wc + (size_t)(d0 + cr) * 1280 + kc * 64 + cseg * 16;
    uint32_t da = aBase + (uint32_t)(buf * 4352 + cr * 68 + cseg * 16) * 4;
    uint32_t db = bBase + (uint32_t)(buf * 4352 + cr * 68 + cseg * 16) * 4;
    #pragma unroll
    for (int j = 0; j < 4; j++) { cp16(da + j * 16, sa + j * 4); cp16(db + j * 16, sb + j * 4); }
    cp_commit();
  };

  float acc[4][4];
  #pragma unroll
  for (int b = 0; b < 4; b++)
    #pragma unroll
    for (int c = 0; c < 4; c++) acc[b][c] = 0.f;

  issue(0, 0);

  for (int kc = 0; kc < 20; kc++) {
    const int buf = kc & 1;
    if (kc + 1 < 20) {
      issue(kc + 1, buf ^ 1);
      asm volatile("cp.async.wait_group 1;");
    } else {
      asm volatile("cp.async.wait_group 0;");
    }
    __syncthreads();

    const float* A = sA3 + buf * 4352;
    const float* B = sB3 + buf * 4352;
    const int R = wm * 16;
    #pragma unroll
    for (int ks = 0; ks < 8; ks++) {
      const int k0 = ks * 8;
      uint32_t a0 = f2tf(A[(R + g    ) * 68 + k0 + q    ]);
      uint32_t a1 = f2tf(A[(R + g + 8) * 68 + k0 + q    ]);
      uint32_t a2 = f2tf(A[(R + g    ) * 68 + k0 + q + 4]);
      uint32_t a3 = f2tf(A[(R + g + 8) * 68 + k0 + q + 4]);
      #pragma unroll
      for (int nb = 0; nb < 4; nb++) {
        const int n = wn * 32 + nb * 8 + g;
        uint32_t b0 = f2tf(B[n * 68 + k0 + q    ]);
        uint32_t b1 = f2tf(B[n * 68 + k0 + q + 4]);
        asm volatile(
          "mma.sync.aligned.m16n8k8.row.col.f32.tf32.tf32.f32 "
          "{%0,%1,%2,%3}, {%4,%5,%6,%7}, {%8,%9}, {%0,%1,%2,%3};\n"
          : "+f"(acc[nb][0]), "+f"(acc[nb][1]), "+f"(acc[nb][2]), "+f"(acc[nb][3])
          : "r"(a0), "r"(a1), "r"(a2), "r"(a3), "r"(b0), "r"(b1));
      }
    }
    __syncthreads();
  }

  const int r0 = t0 + wm * 16 + g;
  #pragma unroll
  for (int nb = 0; nb < 4; nb++) {
    const int c = d0 + wn * 32 + nb * 8 + q * 2;
    float bc0 = bc[c], bc1 = bc[c + 1];
    *(float2*)(out + (size_t)r0 * L + c)       = make_float2(acc[nb][0] + bc0, acc[nb][1] + bc1);
    *(float2*)(out + (size_t)(r0 + 8) * L + c) = make_float2(acc[nb][2] + bc0, acc[nb][3] + bc1);
  }
}

// ---------------- launch ----------------
extern "C" void kernel_launch(void* const* d_in, const int* in_sizes, int n_in,
                              void* d_out, int out_size) {
  const float* s_z    = (const float*)d_in[0];
  const float* s_s_in = (const float*)d_in[1];
  const float* pmask  = (const float*)d_in[2];
  const float* ln_g   = (const float*)d_in[3];
  const float* ln_b   = (const float*)d_in[4];
  const float* w1     = (const float*)d_in[5];
  const float* b1     = (const float*)d_in[6];
  const float* w2     = (const float*)d_in[7];
  const float* b2     = (const float*)d_in[8];
  const float* wc     = (const float*)d_in[9];
  const float* bc     = (const float*)d_in[10];
  float* out = (float*)d_out;

  const int smem1 = 128*136*2 + 64*136*2 + 64*68*4 + (64+64+128+128+128)*4; // 71680
  const int smem2 = 128 * 129 * 4;                                          // 66048
  const int smem3 = 2 * 2 * 64 * 68 * 4;                                    // 69632
  cudaFuncSetAttribute(k_stage1, cudaFuncAttributeMaxDynamicSharedMemorySize, smem1);
  cudaFuncSetAttribute(k_stage2, cudaFuncAttributeMaxDynamicSharedMemorySize, smem2);
  cudaFuncSetAttribute(k_stage3, cudaFuncAttributeMaxDynamicSharedMemorySize, smem3);

  k_masksums<<<L, 256>>>(pmask);
  k_prep<<<1, CZ>>>(w1, b1, ln_g, ln_b);
  k_stage1<<<dim3(NT, NT), 256, smem1>>>(s_z, pmask, ln_g, w1);
  k_stage2<<<128, 256, smem2>>>(w2, b2);
  k_stage3<<<dim3(16, 16), 256, smem3>>>(s_s_in, wc, bc, out);
}